// round 4
// baseline (speedup 1.0000x reference)
#include <cuda_runtime.h>
#include <math.h>
#include <float.h>
#include <stdint.h>

#define Bb 4
#define Nn 8192
#define Ss 2048
#define Kk 64
#define EPSf 1e-5f

#define NCH   16          // FPS chunks
#define CH    128         // steps per chunk
#define WCTAS 128         // worker CTAs
#define TPB   512
#define FCTAS (2*Bb)      // 2 FPS CTAs per batch (cluster pairs)

typedef unsigned long long ull;

// ---------------- device scratch ----------------
__device__ float g_cen[Bb*Ss*3];
__device__ float g_dist[Bb*Nn];
__device__ int   g_cur[Bb];
__device__ float g_wf1[64*67];
__device__ float g_bf1[64];
__device__ float g_wf2[64*64];
__device__ float g_bf2[64];
__device__ float g_wf3[128*64];
__device__ float g_bf3[128];

// ---------------- packed f32x2 helpers (per-lane rn == scalar rn) ----------------
__device__ __forceinline__ ull pk2(float lo, float hi) {
    ull r; asm("mov.b64 %0, {%1, %2};" : "=l"(r) : "f"(lo), "f"(hi)); return r;
}
__device__ __forceinline__ void up2(ull v, float& a, float& b) {
    asm("mov.b64 {%0, %1}, %2;" : "=f"(a), "=f"(b) : "l"(v));
}
__device__ __forceinline__ ull add2(ull a, ull b) {
    ull r; asm("add.rn.f32x2 %0, %1, %2;" : "=l"(r) : "l"(a), "l"(b)); return r;
}
__device__ __forceinline__ ull mul2(ull a, ull b) {
    ull r; asm("mul.rn.f32x2 %0, %1, %2;" : "=l"(r) : "l"(a), "l"(b)); return r;
}

// ---------------- cluster / mbarrier helpers ----------------
__device__ __forceinline__ uint32_t smem_u32(const void* p) {
    uint32_t a;
    asm("{ .reg .u64 t; cvta.to.shared.u64 t, %1; cvt.u32.u64 %0, t; }" : "=r"(a) : "l"(p));
    return a;
}
__device__ __forceinline__ uint32_t mapa_peer(uint32_t laddr, uint32_t rank) {
    uint32_t r;
    asm("mapa.shared::cluster.u32 %0, %1, %2;" : "=r"(r) : "r"(laddr), "r"(rank));
    return r;
}
__device__ __forceinline__ void mbar_init(uint32_t a, unsigned cnt) {
    asm volatile("mbarrier.init.shared.b64 [%0], %1;" :: "r"(a), "r"(cnt) : "memory");
}
__device__ __forceinline__ void st_cluster_u64(uint32_t a, ull v) {
    asm volatile("st.shared::cluster.u64 [%0], %1;" :: "r"(a), "l"(v) : "memory");
}
__device__ __forceinline__ void st_cluster_u32(uint32_t a, unsigned v) {
    asm volatile("st.shared::cluster.u32 [%0], %1;" :: "r"(a), "r"(v) : "memory");
}
__device__ __forceinline__ void mbar_arrive_rel_cluster(uint32_t a) {
    asm volatile("mbarrier.arrive.release.cluster.shared::cluster.b64 _, [%0];" :: "r"(a) : "memory");
}
__device__ __forceinline__ void mbar_wait_cluster(uint32_t a, unsigned parity) {
    unsigned done;
    asm volatile("{\n\t.reg .pred p;\n\t"
        "mbarrier.try_wait.parity.acquire.cluster.shared::cta.b64 p, [%1], %2;\n\t"
        "selp.b32 %0, 1, 0, p;\n\t}"
        : "=r"(done) : "r"(a), "r"(parity) : "memory");
    while (!done) {
        asm volatile("{\n\t.reg .pred p;\n\t"
            "mbarrier.try_wait.parity.acquire.cluster.shared::cta.b64 p, [%1], %2;\n\t"
            "selp.b32 %0, 1, 0, p;\n\t}"
            : "=r"(done) : "r"(a), "r"(parity) : "memory");
    }
}
__device__ __forceinline__ void cluster_sync_() {
    asm volatile("barrier.cluster.arrive.aligned;" ::: "memory");
    asm volatile("barrier.cluster.wait.aligned;" ::: "memory");
}

// ---------------- fold BN into conv + init FPS state ----------------
__global__ void fold_kernel(
    const float* W1, const float* b1, const float* g1, const float* bt1, const float* m1, const float* v1,
    const float* W2, const float* b2, const float* g2, const float* bt2, const float* m2, const float* v2,
    const float* W3, const float* b3, const float* g3, const float* bt3, const float* m3, const float* v3)
{
    int t = threadIdx.x;
    for (int i = t; i < 64*67; i += blockDim.x) {
        int o = i / 67;
        g_wf1[i] = W1[i] * (g1[o] * rsqrtf(v1[o] + EPSf));
    }
    for (int i = t; i < 64; i += blockDim.x)
        g_bf1[i] = (b1[i] - m1[i]) * (g1[i] * rsqrtf(v1[i] + EPSf)) + bt1[i];
    for (int i = t; i < 64*64; i += blockDim.x) {
        int o = i >> 6;
        g_wf2[i] = W2[i] * (g2[o] * rsqrtf(v2[o] + EPSf));
    }
    for (int i = t; i < 64; i += blockDim.x)
        g_bf2[i] = (b2[i] - m2[i]) * (g2[i] * rsqrtf(v2[i] + EPSf)) + bt2[i];
    for (int i = t; i < 128*64; i += blockDim.x) {
        int o = i >> 6;
        g_wf3[i] = W3[i] * (g3[o] * rsqrtf(v3[o] + EPSf));
    }
    for (int i = t; i < 128; i += blockDim.x)
        g_bf3[i] = (b3[i] - m3[i]) * (g3[i] * rsqrtf(v3[i] + EPSf)) + bt3[i];

    for (int i = t; i < Bb*Nn; i += blockDim.x) g_dist[i] = 1e10f;
    if (t < Bb) g_cur[t] = 0;
}

// ---------------- shared-memory layout (floats) : worker view ----------------
#define OW1 0
#define OB1 (OW1 + 64*67)
#define OW2 (OB1 + 64)
#define OB2 (OW2 + 64*65)
#define OW3 (OB2 + 64)
#define OB3 (OW3 + 128*65)
#define OBUF (OB3 + 128)
#define GRP  (67*65 + 64*65)
#define OIDXA (OBUF + 4*GRP)
#define SMEM_FLOATS (OIDXA + 4*64)
#define SMEM_BYTES  (SMEM_FLOATS * 4)
// fps view (raw offsets in same dynamic buffer)
#define F_SX   0
#define F_SY   4096
#define F_SZ   8192
#define F_SVAL 12288            // [2][16] uint
#define F_SIDX (12288 + 32)     // [2][16] uint
#define F_EXCH 12352            // [2] slots x 32B (key u64, cxy u64, cz u32)
#define F_MBAR 12368            // 8B mbarrier

// =====================================================================
// fused pipeline kernel (cluster dim = 2):
//   CTA 0..7    : FPS; batch = blockIdx>>1, rank = blockIdx&1 (cluster pair)
//   CTA 8..135  : ball query + MLP for chunk mlp_chunk
// =====================================================================
__global__ void __launch_bounds__(TPB, 1)
pipe_kernel(const float* __restrict__ x, const float* __restrict__ xc,
            float* __restrict__ out, int fps_chunk, int mlp_chunk)
{
    extern __shared__ float sm[];
    const int tid = threadIdx.x;

    if (blockIdx.x < FCTAS) {
        // ================= FPS (2-CTA cluster per batch) =================
        if (fps_chunk < 0) return;
        const int b    = blockIdx.x >> 1;
        const int rank = blockIdx.x & 1;
        const int HALF = Nn / 2;                   // 4096
        const int half0 = rank * HALF;
        const float* xb   = x + (size_t)b * Nn * 3 + (size_t)half0 * 3;
        const float* xful = x + (size_t)b * Nn * 3;

        float* sx = sm + F_SX;
        float* sy = sm + F_SY;
        float* sz = sm + F_SZ;
        unsigned* svalA = (unsigned*)(sm + F_SVAL);
        unsigned* sidxA = (unsigned*)(sm + F_SIDX);
        ull*      exch  = (ull*)(sm + F_EXCH);     // [2][4] u64 (32B per parity slot)
        uint32_t mbar_l = smem_u32(sm + F_MBAR);
        uint32_t exch_l = smem_u32(sm + F_EXCH);
        const uint32_t peer = rank ^ 1u;
        const uint32_t mbar_r = mapa_peer(mbar_l, peer);
        const uint32_t exch_r = mapa_peer(exch_l, peer);

        // stage own half's coords
        for (int i = tid; i < HALF; i += TPB) {
            sx[i] = xb[i*3 + 0];
            sy[i] = xb[i*3 + 1];
            sz[i] = xb[i*3 + 2];
        }

        // 8 points per thread (4 packed pairs); STATIC reg indexing only
        ull px[4], py[4], pz[4];
        float dist[8];
#pragma unroll
        for (int i = 0; i < 4; i++) {
            int p = tid * 8 + i * 2;
            px[i] = pk2(xb[p*3 + 0], xb[p*3 + 3]);
            py[i] = pk2(xb[p*3 + 1], xb[p*3 + 4]);
            pz[i] = pk2(xb[p*3 + 2], xb[p*3 + 5]);
        }
#pragma unroll
        for (int j = 0; j < 8; j++) dist[j] = g_dist[b*Nn + half0 + tid*8 + j];

        int cur = g_cur[b];
        // current centroid coords from global (uniform broadcast load)
        float cx = xful[cur*3 + 0];
        float cy = xful[cur*3 + 1];
        float cz = xful[cur*3 + 2];

        const int lane = tid & 31;
        const int wrp  = tid >> 5;

        if (tid == 0) mbar_init(mbar_l, 1);
        __syncthreads();
        cluster_sync_();   // peer's mbarrier init complete before any arrive

        const int s0 = fps_chunk * CH;
        for (int si = 0; si < CH; si++) {
            const int s = s0 + si;
            const unsigned par = (unsigned)(si & 1);

            if (rank == 0 && tid == 0) {
                int oc = (b*Ss + s) * 3;
                g_cen[oc+0] = cx; g_cen[oc+1] = cy; g_cen[oc+2] = cz;
                out[oc+0]  = cx; out[oc+1]  = cy; out[oc+2]  = cz;
            }
            const ull ncx = pk2(-cx, -cx);
            const ull ncy = pk2(-cy, -cy);
            const ull ncz = pk2(-cz, -cz);

            float mm[4];
#pragma unroll
            for (int i = 0; i < 4; i++) {
                ull dx = add2(px[i], ncx);
                ull dy = add2(py[i], ncy);
                ull dz = add2(pz[i], ncz);
                ull dd = add2(add2(mul2(dx,dx), mul2(dy,dy)), mul2(dz,dz));
                float d0, d1; up2(dd, d0, d1);
                float n0 = fminf(dist[2*i],   d0);
                float n1 = fminf(dist[2*i+1], d1);
                dist[2*i] = n0; dist[2*i+1] = n1;
                mm[i] = fmaxf(n0, n1);
            }
            float bestv = fmaxf(fmaxf(mm[0], mm[1]), fmaxf(mm[2], mm[3]));

            // warp argmax: max dist bits, then min matching GLOBAL index
            unsigned mv   = __float_as_uint(bestv);
            unsigned wmax = __reduce_max_sync(0xffffffffu, mv);
            unsigned loc  = 0xffffffffu;
            if (mv == wmax) {
                float fm = __uint_as_float(wmax);
#pragma unroll
                for (int j = 7; j >= 0; j--)
                    if (dist[j] == fm) loc = (unsigned)(half0 + tid*8 + j);
            }
            unsigned widx = __reduce_min_sync(0xffffffffu, loc);

            unsigned* sval = svalA + par*16;
            unsigned* sidx = sidxA + par*16;
            if (lane == 0) { sval[wrp] = wmax; sidx[wrp] = widx; }
            __syncthreads();

            unsigned v  = (lane < 16) ? sval[lane] : 0u;
            unsigned id = (lane < 16) ? sidx[lane] : 0xffffffffu;
            unsigned M   = __reduce_max_sync(0xffffffffu, v);
            unsigned cn  = (v == M) ? id : 0xffffffffu;
            unsigned cidx = __reduce_min_sync(0xffffffffu, cn);   // CTA best (global idx, own half)
            const int li = (int)cidx - half0;                     // local index (always in own half)
            ull mkey = ((ull)M << 32) | (ull)(~cidx);

            if (tid == 0) {
                float wcx = sx[li], wcy = sy[li], wcz = sz[li];
                uint32_t slot = exch_r + par*32u;
                st_cluster_u64(slot +  0u, mkey);
                st_cluster_u64(slot +  8u, pk2(wcx, wcy));
                st_cluster_u32(slot + 16u, __float_as_uint(wcz));
                mbar_arrive_rel_cluster(mbar_r);
            }
            mbar_wait_cluster(mbar_l, par);

            ull pkey = exch[par*4 + 0];
            if (pkey > mkey) {
                ull pxy = exch[par*4 + 1];
                up2(pxy, cx, cy);
                cz  = ((float*)exch)[par*8 + 4];
                cur = (int)(~(unsigned)pkey);
            } else {
                cx = sx[li]; cy = sy[li]; cz = sz[li];
                cur = (int)cidx;
            }
        }

        // persist state
#pragma unroll
        for (int j = 0; j < 8; j++) g_dist[b*Nn + half0 + tid*8 + j] = dist[j];
        if (rank == 0 && tid == 0) g_cur[b] = cur;
        return;
    }

    // ================= worker: ball query + MLP =================
    if (mlp_chunk < 0) return;
    const int wcta = blockIdx.x - FCTAS;

    for (int i = tid; i < 64*67; i += TPB) sm[OW1 + i] = g_wf1[i];
    for (int i = tid; i < 64*64; i += TPB) {
        int o = i >> 6, c = i & 63;
        sm[OW2 + o*65 + c] = g_wf2[i];
    }
    for (int i = tid; i < 128*64; i += TPB) {
        int o = i >> 6, c = i & 63;
        sm[OW3 + o*65 + c] = g_wf3[i];
    }
    for (int i = tid; i < 64;  i += TPB) { sm[OB1+i] = g_bf1[i]; sm[OB2+i] = g_bf2[i]; }
    for (int i = tid; i < 128; i += TPB) sm[OB3 + i] = g_bf3[i];

    const int lane = tid & 31;
    const int wrp  = tid >> 5;

    // ---- ball query: warps 0..3, one centroid each ----
    if (wrp < 4) {
        const int lin = wcta * 4 + wrp;
        const int b   = lin >> 7;
        const int s   = mlp_chunk * CH + (lin & 127);
        const int cen = b * Ss + s;
        const float cx = g_cen[cen*3 + 0];
        const float cy = g_cen[cen*3 + 1];
        const float cz = g_cen[cen*3 + 2];
        const float* xb = x + (size_t)b * Nn * 3;
        int* outp = (int*)&sm[OIDXA + wrp*64];

        int count = 0;
        for (int base = 0; base < Nn && count < Kk; base += 32) {
            int p = base + lane;
            float qx = xb[p*3 + 0], qy = xb[p*3 + 1], qz = xb[p*3 + 2];
            float dx = __fsub_rn(cx, qx);
            float dy = __fsub_rn(cy, qy);
            float dz = __fsub_rn(cz, qz);
            float d  = __fadd_rn(__fadd_rn(__fmul_rn(dx,dx), __fmul_rn(dy,dy)),
                                 __fmul_rn(dz,dz));
            bool hit = d < 0.04f;
            unsigned m = __ballot_sync(0xffffffffu, hit);
            int rank2 = __popc(m & ((1u << lane) - 1u));
            if (hit && (count + rank2) < Kk) outp[count + rank2] = p;
            count += __popc(m);
        }
        count = min(count, Kk);
        for (int q = count + lane; q < Kk; q += 32) outp[q] = -1;
    }
    __syncthreads();

    // ---- MLP: 4 warpgroups, one centroid each ----
    const int wgid   = tid >> 7;
    const int wg_tid = tid & 127;
    const int tx = wg_tid & 15;
    const int ty = wg_tid >> 4;
    const int wg_warp = (tid >> 5) & 3;

    const int lin = wcta * 4 + wgid;
    const int b   = lin >> 7;
    const int cen = b * Ss + mlp_chunk * CH + (lin & 127);

    const int OF = OBUF + wgid * GRP;
    const int OH = OF + 67*65;
    int* sidx = (int*)&sm[OIDXA + wgid*64];
    float* pooled = out + (size_t)Bb * Ss * 3;

    const float* xcb = xc + (size_t)b * Nn * 64;
    const float* xb  = x  + (size_t)b * Nn * 3;
    for (int kk = 0; kk < 16; kk++) {
        int k  = wg_warp * 16 + kk;
        int gi = sidx[k];
        gi = gi < 0 ? 0 : gi;
        const float* row = xcb + (size_t)gi * 64;
        sm[OF + lane*65 + k]      = row[lane];
        sm[OF + (lane+32)*65 + k] = row[lane + 32];
        if (lane < 3)
            sm[OF + (64+lane)*65 + k] = xb[gi*3 + lane] - g_cen[cen*3 + lane];
    }
    __syncthreads();

    float acc[8][4];

#pragma unroll
    for (int i = 0; i < 8; i++)
#pragma unroll
        for (int j = 0; j < 4; j++) acc[i][j] = 0.f;
    for (int c = 0; c < 67; c++) {
        float fv[4];
#pragma unroll
        for (int j = 0; j < 4; j++) fv[j] = sm[OF + c*65 + tx*4 + j];
#pragma unroll
        for (int i = 0; i < 8; i++) {
            float wv = sm[OW1 + (ty*8 + i)*67 + c];
#pragma unroll
            for (int j = 0; j < 4; j++) acc[i][j] = fmaf(wv, fv[j], acc[i][j]);
        }
    }
#pragma unroll
    for (int i = 0; i < 8; i++) {
        float bia = sm[OB1 + ty*8 + i];
#pragma unroll
        for (int j = 0; j < 4; j++)
            sm[OH + (ty*8 + i)*65 + tx*4 + j] = fmaxf(acc[i][j] + bia, 0.f);
    }
    __syncthreads();

#pragma unroll
    for (int i = 0; i < 8; i++)
#pragma unroll
        for (int j = 0; j < 4; j++) acc[i][j] = 0.f;
    for (int c = 0; c < 64; c++) {
        float fv[4];
#pragma unroll
        for (int j = 0; j < 4; j++) fv[j] = sm[OH + c*65 + tx*4 + j];
#pragma unroll
        for (int i = 0; i < 8; i++) {
            float wv = sm[OW2 + (ty*8 + i)*65 + c];
#pragma unroll
            for (int j = 0; j < 4; j++) acc[i][j] = fmaf(wv, fv[j], acc[i][j]);
        }
    }
#pragma unroll
    for (int i = 0; i < 8; i++) {
        float bia = sm[OB2 + ty*8 + i];
#pragma unroll
        for (int j = 0; j < 4; j++)
            sm[OF + (ty*8 + i)*65 + tx*4 + j] = fmaxf(acc[i][j] + bia, 0.f);
    }
    __syncthreads();

    for (int op = 0; op < 2; op++) {
#pragma unroll
        for (int i = 0; i < 8; i++)
#pragma unroll
            for (int j = 0; j < 4; j++) acc[i][j] = 0.f;
        for (int c = 0; c < 64; c++) {
            float fv[4];
#pragma unroll
            for (int j = 0; j < 4; j++) fv[j] = sm[OF + c*65 + tx*4 + j];
#pragma unroll
            for (int i = 0; i < 8; i++) {
                float wv = sm[OW3 + (op*64 + ty*8 + i)*65 + c];
#pragma unroll
                for (int j = 0; j < 4; j++) acc[i][j] = fmaf(wv, fv[j], acc[i][j]);
            }
        }
#pragma unroll
        for (int i = 0; i < 8; i++) {
            int o = op*64 + ty*8 + i;
            float bia = sm[OB3 + o];
            float m = -INFINITY;
#pragma unroll
            for (int j = 0; j < 4; j++) {
                int k = tx*4 + j;
                float v = fmaxf(acc[i][j] + bia, 0.f);
                if (sidx[k] >= 0) m = fmaxf(m, v);
            }
#pragma unroll
            for (int off = 8; off; off >>= 1)
                m = fmaxf(m, __shfl_xor_sync(0xffffffffu, m, off, 16));
            if (tx == 0) pooled[(size_t)cen * 128 + o] = m;
        }
    }
}

// ---------------- launch ----------------
static void launch_pipe(const float* x, const float* xc, float* out, int fc, int mc)
{
    cudaLaunchConfig_t cfg = {};
    cfg.gridDim  = dim3(FCTAS + WCTAS, 1, 1);
    cfg.blockDim = dim3(TPB, 1, 1);
    cfg.dynamicSmemBytes = SMEM_BYTES;
    cfg.stream = 0;
    cudaLaunchAttribute attrs[1];
    attrs[0].id = cudaLaunchAttributeClusterDimension;
    attrs[0].val.clusterDim.x = 2;
    attrs[0].val.clusterDim.y = 1;
    attrs[0].val.clusterDim.z = 1;
    cfg.attrs = attrs;
    cfg.numAttrs = 1;
    cudaLaunchKernelEx(&cfg, pipe_kernel, x, xc, out, fc, mc);
}

extern "C" void kernel_launch(void* const* d_in, const int* in_sizes, int n_in,
                              void* d_out, int out_size)
{
    const float* x   = (const float*)d_in[0];
    const float* xc  = (const float*)d_in[1];
    const float* W1  = (const float*)d_in[2];
    const float* b1  = (const float*)d_in[3];
    const float* g1  = (const float*)d_in[4];
    const float* bt1 = (const float*)d_in[5];
    const float* m1  = (const float*)d_in[6];
    const float* v1  = (const float*)d_in[7];
    const float* W2  = (const float*)d_in[8];
    const float* b2  = (const float*)d_in[9];
    const float* g2  = (const float*)d_in[10];
    const float* bt2 = (const float*)d_in[11];
    const float* m2  = (const float*)d_in[12];
    const float* v2  = (const float*)d_in[13];
    const float* W3  = (const float*)d_in[14];
    const float* b3  = (const float*)d_in[15];
    const float* g3  = (const float*)d_in[16];
    const float* bt3 = (const float*)d_in[17];
    const float* m3  = (const float*)d_in[18];
    const float* v3  = (const float*)d_in[19];
    float* out = (float*)d_out;

    fold_kernel<<<1, 256>>>(W1,b1,g1,bt1,m1,v1, W2,b2,g2,bt2,m2,v2, W3,b3,g3,bt3,m3,v3);

    cudaFuncSetAttribute(pipe_kernel, cudaFuncAttributeMaxDynamicSharedMemorySize, SMEM_BYTES);

    launch_pipe(x, xc, out, 0, -1);
    for (int c = 1; c < NCH; c++)
        launch_pipe(x, xc, out, c, c - 1);
    launch_pipe(x, xc, out, -1, NCH - 1);
}